// round 11
// baseline (speedup 1.0000x reference)
#include <cuda_runtime.h>
#include <cuda_bf16.h>
#include <cstdint>

// ---------------- problem constants ----------------
#define BATCH 256
#define LSEQ  256
#define CNODE 128
#define HID   128
#define NHEAD 4
#define DHEAD 32
#define NEDGE 4096
#define NSLOT (NEDGE + CNODE)               // 4224 incl. self loops
#define NNODE (BATCH * CNODE)               // 32768
#define OUT_ELEMS  (BATCH * LSEQ * CNODE)   // 8388608
#define ATTN_ELEMS (BATCH * CNODE * CNODE)  // 4194304

// ---------------- scratch ----------------
__device__ float g_h[NNODE * HID];         // 16 MB  node features
__device__ float g_xl[NNODE * HID];        // 16 MB
__device__ float g_xr[NNODE * HID];        // 16 MB
__device__ int   g_slot_ptr[CNODE + 1];    // slot CSR (self-loop first per dst)
__device__ int   g_slot_src[NSLOT];

// packed f32x2 FMA (ptxas never auto-fuses; must come from PTX)
#define FMA2(d, a, b, c) \
    asm("fma.rn.f32x2 %0, %1, %2, %3;" : "=l"(d) : "l"(a), "l"(b), "l"(c))

__device__ __forceinline__ unsigned long long pack2(float x, float y) {
    unsigned long long r;
    asm("mov.b64 %0, {%1, %2};" : "=l"(r) : "f"(x), "f"(y));
    return r;
}

__device__ __forceinline__ void cp_async16(void* smem_dst, const void* gptr) {
    uint32_t sa = (uint32_t)__cvta_generic_to_shared(smem_dst);
    asm volatile("cp.async.cg.shared.global [%0], [%1], 16;" :: "r"(sa), "l"(gptr));
}
#define CP_COMMIT() asm volatile("cp.async.commit_group;")
#define CP_WAIT0()  asm volatile("cp.async.wait_group 0;")

// ---------------- CSR/slot build ----------------
__global__ void build_csr_kernel(const void* __restrict__ eiraw) {
    __shared__ int cnt[CNODE];
    __shared__ int base[CNODE + 1];
    __shared__ int is64_s;
    const long long* e64 = (const long long*)eiraw;
    const int* e32 = (const int*)eiraw;
    int tid = threadIdx.x;

    if (tid == 0) is64_s = 1;
    if (tid < CNODE) cnt[tid] = 0;
    __syncthreads();
    int bad = 0;
    for (int i = tid; i < NEDGE; i += 256) {
        long long v = e64[i];
        if (v < 0 || v >= CNODE) bad = 1;
    }
    if (bad) is64_s = 0;
    __syncthreads();
    const int is64 = is64_s;

    for (int e = tid; e < NEDGE; e += 256) {
        int d = is64 ? (int)e64[NEDGE + e] : e32[NEDGE + e];
        atomicAdd(&cnt[d], 1);
    }
    __syncthreads();
    if (tid == 0) {
        int run = 0;
        for (int i = 0; i < CNODE; ++i) { base[i] = run; run += cnt[i]; }
        base[CNODE] = run;
    }
    __syncthreads();
    if (tid <= CNODE) g_slot_ptr[tid] = base[tid] + tid;
    if (tid < CNODE) {
        g_slot_src[base[tid] + tid] = tid;   // self loop first
        cnt[tid] = base[tid];
    }
    __syncthreads();
    for (int e = tid; e < NEDGE; e += 256) {
        int d = is64 ? (int)e64[NEDGE + e] : e32[NEDGE + e];
        int s = is64 ? (int)e64[e]         : e32[e];
        int pos = atomicAdd(&cnt[d], 1);
        g_slot_src[pos + d + 1] = s;
    }
}

// ---------------- fused GEMM ----------------
// C(64x128 tile) = A(MxK) @ W(KxN) + bias; double-buffered cp.async, one sync/chunk.
// B smem is row-major [32k][128n] (cp.async direct); dual-k f32x2 operands are
// built with mov.b64 from two row values. Thread owns n = 4tx..4tx+3 (LDS.128).
// MODE 0: A row-major, C row-major.  MODE 1: fused input transpose from x.
// MODE 2: fused output transpose to out[b][l][c].
// DUAL: blockIdx.x selects (W,bias,C) vs (W2,bias2,C2), n0=0.
#define AST 36                      // A_s row stride (floats): 144 B, 16|144
template <int MODE, bool DUAL>
__global__ __launch_bounds__(256, 2) void gemm_t(
    const float* __restrict__ A, int lda,
    const float* __restrict__ W, int ldb,
    const float* __restrict__ bias,
    float* __restrict__ C, int ldc, int K,
    const float* __restrict__ W2, const float* __restrict__ bias2,
    float* __restrict__ C2)
{
    __shared__ __align__(16) float smem_all[12800];   // 50 KB
    float* const As0 = smem_all;                      // 64 x 36
    float* const As1 = smem_all + 2304;
    float* const Bs0 = smem_all + 4608;               // 32 x 128 row-major
    float* const Bs1 = smem_all + 8704;

    const int tid = threadIdx.x;
    const int tx = tid & 31, ty = tid >> 5;
    const int m0 = blockIdx.y * 64;
    int n0;
    const float* Wp = W; const float* bp = bias; float* Cp = C;
    if (DUAL) {
        n0 = 0;
        if (blockIdx.x) { Wp = W2; bp = bias2; Cp = C2; }
    } else {
        n0 = blockIdx.x * 128;
    }

    unsigned long long acc[8][4];
    #pragma unroll
    for (int i = 0; i < 8; ++i)
        #pragma unroll
        for (int j = 0; j < 4; ++j) acc[i][j] = 0ull;

    const int nc = K >> 5;
    float4 aR[2];                                     // MODE 1 only

    // ---- prologue: chunk 0 loads ----
    if (MODE == 1) {
        const float* xb = A + (size_t)(m0 >> 7) * (LSEQ * CNODE) + (m0 & 127);
        #pragma unroll
        for (int r = 0; r < 2; ++r) {
            int f4 = tid + r * 256;
            int kk = f4 >> 4, mq = f4 & 15;
            aR[r] = *(const float4*)(xb + (size_t)kk * CNODE + mq * 4);
        }
    } else {
        #pragma unroll
        for (int r = 0; r < 2; ++r) {
            int f4 = tid + r * 256;
            int m = f4 >> 3, kq = f4 & 7;
            cp_async16(As0 + m * AST + kq * 4, A + (size_t)(m0 + m) * lda + kq * 4);
        }
    }
    #pragma unroll
    for (int r = 0; r < 4; ++r) {
        int f4 = tid + r * 256;
        int kk = f4 >> 5, nq = f4 & 31;
        cp_async16(Bs0 + kk * 128 + nq * 4, Wp + (size_t)kk * ldb + n0 + nq * 4);
    }
    CP_COMMIT();

    for (int c = 0; c < nc; ++c) {
        float* Ab = (c & 1) ? As1 : As0;
        float* Bb = (c & 1) ? Bs1 : Bs0;
        if (MODE == 1) {
            #pragma unroll
            for (int r = 0; r < 2; ++r) {
                int f4 = tid + r * 256;
                int kk = f4 >> 4, mq = f4 & 15;
                float* p = Ab + kk;
                p[(mq * 4 + 0) * AST] = aR[r].x;
                p[(mq * 4 + 1) * AST] = aR[r].y;
                p[(mq * 4 + 2) * AST] = aR[r].z;
                p[(mq * 4 + 3) * AST] = aR[r].w;
            }
        }
        CP_WAIT0();
        __syncthreads();
        // ---- issue next chunk's loads (overlap with compute) ----
        if (c + 1 < nc) {
            const int k0 = (c + 1) << 5;
            float* An = (c & 1) ? As0 : As1;
            float* Bn = (c & 1) ? Bs0 : Bs1;
            if (MODE == 1) {
                const float* xb = A + (size_t)(m0 >> 7) * (LSEQ * CNODE) + (m0 & 127);
                #pragma unroll
                for (int r = 0; r < 2; ++r) {
                    int f4 = tid + r * 256;
                    int kk = f4 >> 4, mq = f4 & 15;
                    aR[r] = *(const float4*)(xb + (size_t)(k0 + kk) * CNODE + mq * 4);
                }
            } else {
                #pragma unroll
                for (int r = 0; r < 2; ++r) {
                    int f4 = tid + r * 256;
                    int m = f4 >> 3, kq = f4 & 7;
                    cp_async16(An + m * AST + kq * 4,
                               A + (size_t)(m0 + m) * lda + k0 + kq * 4);
                }
            }
            #pragma unroll
            for (int r = 0; r < 4; ++r) {
                int f4 = tid + r * 256;
                int kk = f4 >> 5, nq = f4 & 31;
                cp_async16(Bn + kk * 128 + nq * 4,
                           Wp + (size_t)(k0 + kk) * ldb + n0 + nq * 4);
            }
            CP_COMMIT();
        }
        // ---- compute: 8 kp-pairs (4 k each) ----
        #pragma unroll
        for (int kp2 = 0; kp2 < 8; ++kp2) {
            const float* Bk = Bb + kp2 * 512 + tx * 4;
            float4 re0 = *(const float4*)(Bk);          // k = 4kp2
            float4 ro0 = *(const float4*)(Bk + 128);    // k = 4kp2+1
            float4 re1 = *(const float4*)(Bk + 256);    // k = 4kp2+2
            float4 ro1 = *(const float4*)(Bk + 384);    // k = 4kp2+3
            unsigned long long b0[4], b1[4];
            b0[0] = pack2(re0.x, ro0.x); b0[1] = pack2(re0.y, ro0.y);
            b0[2] = pack2(re0.z, ro0.z); b0[3] = pack2(re0.w, ro0.w);
            b1[0] = pack2(re1.x, ro1.x); b1[1] = pack2(re1.y, ro1.y);
            b1[2] = pack2(re1.z, ro1.z); b1[3] = pack2(re1.w, ro1.w);
            #pragma unroll
            for (int i = 0; i < 8; ++i) {
                float4 a4 = *(const float4*)(Ab + (ty * 8 + i) * AST + kp2 * 4);
                unsigned long long ae = pack2(a4.x, a4.y);
                unsigned long long ao = pack2(a4.z, a4.w);
                #pragma unroll
                for (int j = 0; j < 4; ++j) FMA2(acc[i][j], ae, b0[j], acc[i][j]);
                #pragma unroll
                for (int j = 0; j < 4; ++j) FMA2(acc[i][j], ao, b1[j], acc[i][j]);
            }
        }
    }

    const float4 bias4 = *(const float4*)(bp + n0 + tx * 4);
    if (MODE != 2) {
        #pragma unroll
        for (int i = 0; i < 8; ++i) {
            int m = m0 + ty * 8 + i;
            float2 p0 = *(float2*)&acc[i][0];
            float2 p1 = *(float2*)&acc[i][1];
            float2 p2 = *(float2*)&acc[i][2];
            float2 p3 = *(float2*)&acc[i][3];
            float4 o;
            o.x = p0.x + p0.y + bias4.x;
            o.y = p1.x + p1.y + bias4.y;
            o.z = p2.x + p2.y + bias4.z;
            o.w = p3.x + p3.y + bias4.w;
            *(float4*)(Cp + (size_t)m * ldc + n0 + tx * 4) = o;
        }
    } else {
        __syncthreads();                              // everyone done reading smem
        float* Cs = smem_all;                         // [64 c][128 l] stride 129
        #pragma unroll
        for (int i = 0; i < 8; ++i) {
            float* row = Cs + (ty * 8 + i) * 129 + tx * 4;
            float2 p0 = *(float2*)&acc[i][0];
            float2 p1 = *(float2*)&acc[i][1];
            float2 p2 = *(float2*)&acc[i][2];
            float2 p3 = *(float2*)&acc[i][3];
            row[0] = p0.x + p0.y + bias4.x;
            row[1] = p1.x + p1.y + bias4.y;
            row[2] = p2.x + p2.y + bias4.z;
            row[3] = p3.x + p3.y + bias4.w;
        }
        __syncthreads();
        const int b = m0 >> 7, c0 = m0 & 127;
        float* ob = Cp + (size_t)b * (LSEQ * CNODE) + c0;
        #pragma unroll
        for (int rep = 0; rep < 8; ++rep) {
            int l = rep * 16 + (tid >> 4);
            int ci = (tid & 15) * 4;
            float4 v;
            v.x = Cs[(ci + 0) * 129 + l];
            v.y = Cs[(ci + 1) * 129 + l];
            v.z = Cs[(ci + 2) * 129 + l];
            v.w = Cs[(ci + 3) * 129 + l];
            *(float4*)(ob + (size_t)(n0 + l) * CNODE + ci) = v;
        }
    }
}

// ---------------- GAT layer kernel (warp-per-dst, all warp-local) ----------------
#define XL_F     (CNODE * 132)                 // 16896
#define LBUF_F   (16 * 128 * 4)                // 8192
#define ATTN_F   (16 * 128)                    // 2048
#define A_F      128
#define SMEM_F   (XL_F + LBUF_F + ATTN_F + A_F)
#define SRC_B_OFF (SMEM_F * 4)
#define PTR_B_OFF (SRC_B_OFF + NSLOT)
#define GAT_SMEM_BYTES (PTR_B_OFF + (CNODE + 1) * 4)

__global__ __launch_bounds__(512, 2) void gat_kernel(
    float* __restrict__ h, const float* __restrict__ xl, const float* __restrict__ xr,
    const float* __restrict__ att, const float* __restrict__ gat_bias,
    const float* __restrict__ ln_g, const float* __restrict__ ln_b,
    float* __restrict__ attn_out)
{
    extern __shared__ __align__(16) float sm[];
    float* xl_s   = sm;
    float* lbuf   = sm + XL_F;
    float* attnrow= sm + XL_F + LBUF_F;
    float* a_s    = sm + XL_F + LBUF_F + ATTN_F;
    unsigned char* src8 = (unsigned char*)sm + SRC_B_OFF;
    int* ptr_s = (int*)((char*)sm + PTR_B_OFF);

    const int b = blockIdx.x;
    const int tid = threadIdx.x;
    const int w = tid >> 5;
    const int l = tid & 31;
    const int hh = l >> 3;

    {
        const float4* src4 = (const float4*)(xl + (size_t)b * CNODE * HID);
        for (int i = tid; i < CNODE * 32; i += 512) {
            int node = i >> 5, d4 = i & 31;
            ((float4*)xl_s)[node * 33 + d4] = src4[i];
        }
        for (int i = tid; i < NSLOT; i += 512) src8[i] = (unsigned char)g_slot_src[i];
        if (tid <= CNODE) ptr_s[tid] = g_slot_ptr[tid];
        if (tid < 128) a_s[tid] = att[tid];
    }
    __syncthreads();

    const float4 a4 = ((const float4*)a_s)[l];
    const float4 bias4 = ((const float4*)gat_bias)[l];
    const float4 g4v = ((const float4*)ln_g)[l];
    const float4 b4v = ((const float4*)ln_b)[l];
    float* mybuf = lbuf + w * 512;
    const float4* xls4 = (const float4*)xl_s;

    for (int d = w; d < CNODE; d += 16) {
        const int sb = ptr_s[d];
        int E1 = ptr_s[d + 1] - sb;
        if (E1 > 128) E1 = 128;
        const size_t node = (size_t)b * CNODE + d;
        const float4 xr4 = ((const float4*)(xr + node * HID))[l];

        float m = -1e30f;
        #pragma unroll 2
        for (int k = 0; k < E1; ++k) {
            const int src = src8[sb + k];
            const float4 v = xls4[src * 33 + l];
            float p;
            {
                float t0 = v.x + xr4.x; t0 = fmaxf(t0, 0.2f * t0);
                float t1 = v.y + xr4.y; t1 = fmaxf(t1, 0.2f * t1);
                float t2 = v.z + xr4.z; t2 = fmaxf(t2, 0.2f * t2);
                float t3 = v.w + xr4.w; t3 = fmaxf(t3, 0.2f * t3);
                p = t0 * a4.x + t1 * a4.y + t2 * a4.z + t3 * a4.w;
            }
            p += __shfl_xor_sync(0xffffffffu, p, 4);
            p += __shfl_xor_sync(0xffffffffu, p, 2);
            p += __shfl_xor_sync(0xffffffffu, p, 1);
            if ((l & 7) == 0) mybuf[k * 4 + hh] = p;
            m = fmaxf(m, p);
        }
        __syncwarp();
        float4 m4;
        m4.x = __shfl_sync(0xffffffffu, m, 0);
        m4.y = __shfl_sync(0xffffffffu, m, 8);
        m4.z = __shfl_sync(0xffffffffu, m, 16);
        m4.w = __shfl_sync(0xffffffffu, m, 24);

        float4 s4 = {0.f, 0.f, 0.f, 0.f};
        for (int k = l; k < E1; k += 32) {
            float4 f = ((float4*)mybuf)[k];
            f.x = __expf(f.x - m4.x);
            f.y = __expf(f.y - m4.y);
            f.z = __expf(f.z - m4.z);
            f.w = __expf(f.w - m4.w);
            ((float4*)mybuf)[k] = f;
            s4.x += f.x; s4.y += f.y; s4.z += f.z; s4.w += f.w;
        }
        #pragma unroll
        for (int o = 16; o; o >>= 1) {
            s4.x += __shfl_xor_sync(0xffffffffu, s4.x, o);
            s4.y += __shfl_xor_sync(0xffffffffu, s4.y, o);
            s4.z += __shfl_xor_sync(0xffffffffu, s4.z, o);
            s4.w += __shfl_xor_sync(0xffffffffu, s4.w, o);
        }
        float4 rs4;
        rs4.x = 1.0f / (s4.x + 1e-16f);
        rs4.y = 1.0f / (s4.y + 1e-16f);
        rs4.z = 1.0f / (s4.z + 1e-16f);
        rs4.w = 1.0f / (s4.w + 1e-16f);
        const float rs_m = (hh == 0) ? rs4.x : (hh == 1) ? rs4.y : (hh == 2) ? rs4.z : rs4.w;
        __syncwarp();

        float4 acc = {0.f, 0.f, 0.f, 0.f};
        #pragma unroll 2
        for (int k = 0; k < E1; ++k) {
            const int src = src8[sb + k];
            const float e = mybuf[k * 4 + hh];
            const float4 v = xls4[src * 33 + l];
            acc.x += e * v.x; acc.y += e * v.y; acc.z += e * v.z; acc.w += e * v.w;
        }
        float4 gout;
        gout.x = acc.x * rs_m + bias4.x;
        gout.y = acc.y * rs_m + bias4.y;
        gout.z = acc.z * rs_m + bias4.z;
        gout.w = acc.w * rs_m + bias4.w;
        gout.x = (gout.x > 0.f) ? gout.x : (__expf(gout.x) - 1.f);
        gout.y = (gout.y > 0.f) ? gout.y : (__expf(gout.y) - 1.f);
        gout.z = (gout.z > 0.f) ? gout.z : (__expf(gout.z) - 1.f);
        gout.w = (gout.w > 0.f) ? gout.w : (__expf(gout.w) - 1.f);
        float4 hv = ((const float4*)(h + node * HID))[l];
        hv.x += gout.x; hv.y += gout.y; hv.z += gout.z; hv.w += gout.w;
        float sum = hv.x + hv.y + hv.z + hv.w;
        float sq  = hv.x*hv.x + hv.y*hv.y + hv.z*hv.z + hv.w*hv.w;
        #pragma unroll
        for (int o = 16; o; o >>= 1) {
            sum += __shfl_xor_sync(0xffffffffu, sum, o);
            sq  += __shfl_xor_sync(0xffffffffu, sq, o);
        }
        const float mu = sum * (1.0f / 128.0f);
        const float var = sq * (1.0f / 128.0f) - mu * mu;
        const float inv = rsqrtf(var + 1e-5f);
        float4 ho;
        ho.x = (hv.x - mu) * inv * g4v.x + b4v.x;
        ho.y = (hv.y - mu) * inv * g4v.y + b4v.y;
        ho.z = (hv.z - mu) * inv * g4v.z + b4v.z;
        ho.w = (hv.w - mu) * inv * g4v.w + b4v.w;
        ((float4*)(h + node * HID))[l] = ho;

        if (attn_out) {
            float* row = attnrow + w * 128;
            ((float4*)row)[l] = make_float4(0.f, 0.f, 0.f, 0.f);
            __syncwarp();
            for (int k = l; k < E1; k += 32) {
                const float4 e4 = ((float4*)mybuf)[k];
                const float val = 0.25f * (e4.x * rs4.x + e4.y * rs4.y +
                                           e4.z * rs4.z + e4.w * rs4.w);
                atomicAdd(&row[src8[sb + k]], val);
            }
            __syncwarp();
            ((float4*)(attn_out + (size_t)b * CNODE * CNODE + (size_t)d * CNODE))[l] =
                ((float4*)row)[l];
            __syncwarp();
        }
    }
}

// ---------------- launch ----------------
extern "C" void kernel_launch(void* const* d_in, const int* in_sizes, int n_in,
                              void* d_out, int out_size) {
    const float* x        = (const float*)d_in[0];
    const void*  ei       = d_in[1];
    const float* emb_W    = (const float*)d_in[2];
    const float* emb_b    = (const float*)d_in[3];
    const float* lin_l_W  = (const float*)d_in[4];
    const float* lin_l_b  = (const float*)d_in[5];
    const float* lin_r_W  = (const float*)d_in[6];
    const float* lin_r_b  = (const float*)d_in[7];
    const float* att      = (const float*)d_in[8];
    const float* gat_bias = (const float*)d_in[9];
    const float* ln_g     = (const float*)d_in[10];
    const float* ln_b     = (const float*)d_in[11];
    const float* proj_W   = (const float*)d_in[12];
    const float* proj_b   = (const float*)d_in[13];
    float* out = (float*)d_out;

    float *h, *xl, *xr;
    cudaGetSymbolAddress((void**)&h,  g_h);
    cudaGetSymbolAddress((void**)&xl, g_xl);
    cudaGetSymbolAddress((void**)&xr, g_xr);

    cudaFuncSetAttribute(gat_kernel, cudaFuncAttributeMaxDynamicSharedMemorySize, GAT_SMEM_BYTES);

    build_csr_kernel<<<1, 256>>>(ei);

    // embed (fused input transpose): h = xT @ emb_W + emb_b
    gemm_t<1, false><<<dim3(1, NNODE / 64), 256>>>(x, 0, emb_W, HID, emb_b, h, HID, LSEQ,
                                                   nullptr, nullptr, nullptr);

    for (int layer = 0; layer < 2; ++layer) {
        // lin_l and lin_r fused into one dual launch
        gemm_t<0, true><<<dim3(2, NNODE / 64), 256>>>(
            h, HID, lin_l_W + layer * HID * HID, HID, lin_l_b + layer * HID, xl, HID, HID,
            lin_r_W + layer * HID * HID, lin_r_b + layer * HID, xr);
        float* attn_ptr = (layer == 1 && out_size >= OUT_ELEMS + ATTN_ELEMS) ? out + OUT_ELEMS : nullptr;
        gat_kernel<<<BATCH, 512, GAT_SMEM_BYTES>>>(h, xl, xr,
                                                   att + layer * HID, gat_bias + layer * HID,
                                                   ln_g + layer * HID, ln_b + layer * HID, attn_ptr);
    }

    // proj (fused output transpose): out = (h @ proj_W + proj_b) transposed
    gemm_t<2, false><<<dim3(2, NNODE / 64), 256>>>(h, HID, proj_W, LSEQ, proj_b, out, 0, HID,
                                                   nullptr, nullptr, nullptr);
}

// round 14
// speedup vs baseline: 1.0042x; 1.0042x over previous
#include <cuda_runtime.h>
#include <cuda_bf16.h>
#include <cstdint>

// ---------------- problem constants ----------------
#define BATCH 256
#define LSEQ  256
#define CNODE 128
#define HID   128
#define NHEAD 4
#define DHEAD 32
#define NEDGE 4096
#define NSLOT (NEDGE + CNODE)               // 4224 incl. self loops
#define NNODE (BATCH * CNODE)               // 32768
#define OUT_ELEMS  (BATCH * LSEQ * CNODE)   // 8388608
#define ATTN_ELEMS (BATCH * CNODE * CNODE)  // 4194304

// ---------------- scratch ----------------
__device__ float g_Xt[NNODE * LSEQ];       // 32 MB  transposed x for embed GEMM
__device__ float g_h[NNODE * HID];         // 16 MB  node features
__device__ float g_xl[NNODE * HID];        // 16 MB
__device__ float g_xr[NNODE * HID];        // 16 MB
__device__ float g_om[NNODE * LSEQ];       // 32 MB  proj output before transpose
__device__ int   g_slot_ptr[CNODE + 1];    // slot CSR (self-loop first per dst)
__device__ int   g_slot_src[NSLOT];

// packed f32x2 FMA (ptxas never auto-fuses; must come from PTX)
#define FMA2(d, a, b, c) \
    asm("fma.rn.f32x2 %0, %1, %2, %3;" : "=l"(d) : "l"(a), "l"(b), "l"(c))

// ---------------- CSR/slot build ----------------
__global__ void build_csr_kernel(const void* __restrict__ eiraw) {
    __shared__ int cnt[CNODE];
    __shared__ int base[CNODE + 1];
    __shared__ int is64_s;
    const long long* e64 = (const long long*)eiraw;
    const int* e32 = (const int*)eiraw;
    int tid = threadIdx.x;

    if (tid == 0) is64_s = 1;
    if (tid < CNODE) cnt[tid] = 0;
    __syncthreads();
    int bad = 0;
    for (int i = tid; i < NEDGE; i += 256) {
        long long v = e64[i];
        if (v < 0 || v >= CNODE) bad = 1;
    }
    if (bad) is64_s = 0;
    __syncthreads();
    const int is64 = is64_s;

    for (int e = tid; e < NEDGE; e += 256) {
        int d = is64 ? (int)e64[NEDGE + e] : e32[NEDGE + e];
        atomicAdd(&cnt[d], 1);
    }
    __syncthreads();
    if (tid == 0) {
        int run = 0;
        for (int i = 0; i < CNODE; ++i) { base[i] = run; run += cnt[i]; }
        base[CNODE] = run;
    }
    __syncthreads();
    if (tid <= CNODE) g_slot_ptr[tid] = base[tid] + tid;
    if (tid < CNODE) {
        g_slot_src[base[tid] + tid] = tid;   // self loop first
        cnt[tid] = base[tid];
    }
    __syncthreads();
    for (int e = tid; e < NEDGE; e += 256) {
        int d = is64 ? (int)e64[NEDGE + e] : e32[NEDGE + e];
        int s = is64 ? (int)e64[e]         : e32[e];
        int pos = atomicAdd(&cnt[d], 1);
        g_slot_src[pos + d + 1] = s;
    }
}

// ---------------- transpose x: (B,L,C) -> Xt[(b*C+c)][l] ----------------
__global__ void transpose_x_kernel(const float* __restrict__ x) {
    __shared__ float tile[32][33];
    int b = blockIdx.z;
    int l0 = blockIdx.x * 32, c0 = blockIdx.y * 32;
    int tx = threadIdx.x, ty = threadIdx.y;
    const float* src = x + (size_t)b * LSEQ * CNODE;
    #pragma unroll
    for (int i = 0; i < 32; i += 8)
        tile[ty + i][tx] = src[(size_t)(l0 + ty + i) * CNODE + c0 + tx];
    __syncthreads();
    float* dst = g_Xt + (size_t)b * CNODE * LSEQ;
    #pragma unroll
    for (int i = 0; i < 32; i += 8)
        dst[(size_t)(c0 + ty + i) * LSEQ + l0 + tx] = tile[tx][ty + i];
}

// ---------------- transpose out: om[(b*C+c)][l] -> out[(b*L+l)][c] ----------------
__global__ void transpose_out_kernel(float* __restrict__ out) {
    __shared__ float tile[32][33];
    int b = blockIdx.z;
    int l0 = blockIdx.x * 32, c0 = blockIdx.y * 32;
    int tx = threadIdx.x, ty = threadIdx.y;
    const float* src = g_om + (size_t)b * CNODE * LSEQ;
    #pragma unroll
    for (int i = 0; i < 32; i += 8)
        tile[ty + i][tx] = src[(size_t)(c0 + ty + i) * LSEQ + l0 + tx];
    __syncthreads();
    float* dst = out + (size_t)b * LSEQ * CNODE;
    #pragma unroll
    for (int i = 0; i < 32; i += 8)
        dst[(size_t)(l0 + ty + i) * CNODE + c0 + tx] = tile[tx][ty + i];
}

// ---------------- fp32 GEMM, C = A(MxK) @ W(KxN) + bias ----------------
// tile 32(M) x 128(N), K chunked by 32, dual-k f32x2 accumulators.
// Small thread-tile (4x4 pairs = 32 acc regs) -> ~3 CTAs/SM for latency hiding.
// grid: (N/128, M/32), block 256.
__global__ __launch_bounds__(256, 3) void gemm_kernel(
    const float* __restrict__ A, int lda,
    const float* __restrict__ W, int ldb,
    const float* __restrict__ bias,
    float* __restrict__ C, int ldc, int K)
{
    __shared__ __align__(16) float A_s[32 * 32];
    __shared__ __align__(16) unsigned long long B_s[16 * 128]; // pair-major
    const int tid = threadIdx.x;
    const int tx = tid & 31, ty = tid >> 5;     // ty: 0..7
    const int m0 = blockIdx.y * 32;
    const int n0 = blockIdx.x * 128;

    unsigned long long acc[4][4];
    #pragma unroll
    for (int i = 0; i < 4; ++i)
        #pragma unroll
        for (int j = 0; j < 4; ++j) acc[i][j] = 0ull;

    float* B_f = (float*)B_s;
    for (int k0 = 0; k0 < K; k0 += 32) {
        {   // A: one float4 per thread (32 rows x 8 quads)
            int m = tid >> 3, kq = tid & 7;
            *(float4*)(A_s + m * 32 + kq * 4) =
                *(const float4*)(A + (size_t)(m0 + m) * lda + k0 + kq * 4);
        }
        #pragma unroll
        for (int i = 0; i < 16; ++i) {
            int idx = tid + i * 256;
            int kk = idx >> 7;
            int nn = idx & 127;
            B_f[(kk >> 1) * 256 + nn * 2 + (kk & 1)] = W[(size_t)(k0 + kk) * ldb + n0 + nn];
        }
        __syncthreads();
        #pragma unroll
        for (int kp = 0; kp < 16; ++kp) {
            unsigned long long b2[4];
            #pragma unroll
            for (int j = 0; j < 4; ++j)
                b2[j] = B_s[kp * 128 + tx + j * 32];
            #pragma unroll
            for (int i = 0; i < 4; ++i) {
                unsigned long long a2 = *(const unsigned long long*)(A_s + (ty * 4 + i) * 32 + kp * 2);
                #pragma unroll
                for (int j = 0; j < 4; ++j)
                    FMA2(acc[i][j], a2, b2[j], acc[i][j]);
            }
        }
        __syncthreads();
    }
    #pragma unroll
    for (int i = 0; i < 4; ++i) {
        int m = m0 + ty * 4 + i;
        #pragma unroll
        for (int j = 0; j < 4; ++j) {
            int n = n0 + tx + j * 32;
            float2 p = *(float2*)&acc[i][j];
            C[(size_t)m * ldc + n] = p.x + p.y + bias[n];
        }
    }
}

// ---------------- GAT layer kernel (warp-per-dst, all warp-local) ----------------
#define XL_F     (CNODE * 132)                 // 16896
#define LBUF_F   (16 * 128 * 4)                // 8192
#define ATTN_F   (16 * 128)                    // 2048
#define A_F      128
#define SMEM_F   (XL_F + LBUF_F + ATTN_F + A_F)
#define SRC_B_OFF (SMEM_F * 4)
#define PTR_B_OFF (SRC_B_OFF + NSLOT)
#define GAT_SMEM_BYTES (PTR_B_OFF + (CNODE + 1) * 4)

__global__ __launch_bounds__(512, 2) void gat_kernel(
    float* __restrict__ h, const float* __restrict__ xl, const float* __restrict__ xr,
    const float* __restrict__ att, const float* __restrict__ gat_bias,
    const float* __restrict__ ln_g, const float* __restrict__ ln_b,
    float* __restrict__ attn_out)
{
    extern __shared__ __align__(16) float sm[];
    float* xl_s   = sm;
    float* lbuf   = sm + XL_F;
    float* attnrow= sm + XL_F + LBUF_F;
    float* a_s    = sm + XL_F + LBUF_F + ATTN_F;
    unsigned char* src8 = (unsigned char*)sm + SRC_B_OFF;
    int* ptr_s = (int*)((char*)sm + PTR_B_OFF);

    const int b = blockIdx.x;
    const int tid = threadIdx.x;
    const int w = tid >> 5;
    const int l = tid & 31;
    const int hh = l >> 3;

    {
        const float4* src4 = (const float4*)(xl + (size_t)b * CNODE * HID);
        for (int i = tid; i < CNODE * 32; i += 512) {
            int node = i >> 5, d4 = i & 31;
            ((float4*)xl_s)[node * 33 + d4] = src4[i];
        }
        for (int i = tid; i < NSLOT; i += 512) src8[i] = (unsigned char)g_slot_src[i];
        if (tid <= CNODE) ptr_s[tid] = g_slot_ptr[tid];
        if (tid < 128) a_s[tid] = att[tid];
    }
    __syncthreads();

    const float4 a4 = ((const float4*)a_s)[l];
    const float4 bias4 = ((const float4*)gat_bias)[l];
    const float4 g4v = ((const float4*)ln_g)[l];
    const float4 b4v = ((const float4*)ln_b)[l];
    float* mybuf = lbuf + w * 512;
    const float4* xls4 = (const float4*)xl_s;

    for (int d = w; d < CNODE; d += 16) {
        const int sb = ptr_s[d];
        int E1 = ptr_s[d + 1] - sb;
        if (E1 > 128) E1 = 128;
        const size_t node = (size_t)b * CNODE + d;
        const float4 xr4 = ((const float4*)(xr + node * HID))[l];

        float m = -1e30f;
        #pragma unroll 2
        for (int k = 0; k < E1; ++k) {
            const int src = src8[sb + k];
            const float4 v = xls4[src * 33 + l];
            float p;
            {
                float t0 = v.x + xr4.x; t0 = fmaxf(t0, 0.2f * t0);
                float t1 = v.y + xr4.y; t1 = fmaxf(t1, 0.2f * t1);
                float t2 = v.z + xr4.z; t2 = fmaxf(t2, 0.2f * t2);
                float t3 = v.w + xr4.w; t3 = fmaxf(t3, 0.2f * t3);
                p = t0 * a4.x + t1 * a4.y + t2 * a4.z + t3 * a4.w;
            }
            p += __shfl_xor_sync(0xffffffffu, p, 4);
            p += __shfl_xor_sync(0xffffffffu, p, 2);
            p += __shfl_xor_sync(0xffffffffu, p, 1);
            if ((l & 7) == 0) mybuf[k * 4 + hh] = p;
            m = fmaxf(m, p);
        }
        __syncwarp();
        float4 m4;
        m4.x = __shfl_sync(0xffffffffu, m, 0);
        m4.y = __shfl_sync(0xffffffffu, m, 8);
        m4.z = __shfl_sync(0xffffffffu, m, 16);
        m4.w = __shfl_sync(0xffffffffu, m, 24);

        float4 s4 = {0.f, 0.f, 0.f, 0.f};
        for (int k = l; k < E1; k += 32) {
            float4 f = ((float4*)mybuf)[k];
            f.x = __expf(f.x - m4.x);
            f.y = __expf(f.y - m4.y);
            f.z = __expf(f.z - m4.z);
            f.w = __expf(f.w - m4.w);
            ((float4*)mybuf)[k] = f;
            s4.x += f.x; s4.y += f.y; s4.z += f.z; s4.w += f.w;
        }
        #pragma unroll
        for (int o = 16; o; o >>= 1) {
            s4.x += __shfl_xor_sync(0xffffffffu, s4.x, o);
            s4.y += __shfl_xor_sync(0xffffffffu, s4.y, o);
            s4.z += __shfl_xor_sync(0xffffffffu, s4.z, o);
            s4.w += __shfl_xor_sync(0xffffffffu, s4.w, o);
        }
        float4 rs4;
        rs4.x = 1.0f / (s4.x + 1e-16f);
        rs4.y = 1.0f / (s4.y + 1e-16f);
        rs4.z = 1.0f / (s4.z + 1e-16f);
        rs4.w = 1.0f / (s4.w + 1e-16f);
        const float rs_m = (hh == 0) ? rs4.x : (hh == 1) ? rs4.y : (hh == 2) ? rs4.z : rs4.w;
        __syncwarp();

        float4 acc = {0.f, 0.f, 0.f, 0.f};
        #pragma unroll 2
        for (int k = 0; k < E1; ++k) {
            const int src = src8[sb + k];
            const float e = mybuf[k * 4 + hh];
            const float4 v = xls4[src * 33 + l];
            acc.x += e * v.x; acc.y += e * v.y; acc.z += e * v.z; acc.w += e * v.w;
        }
        float4 gout;
        gout.x = acc.x * rs_m + bias4.x;
        gout.y = acc.y * rs_m + bias4.y;
        gout.z = acc.z * rs_m + bias4.z;
        gout.w = acc.w * rs_m + bias4.w;
        gout.x = (gout.x > 0.f) ? gout.x : (__expf(gout.x) - 1.f);
        gout.y = (gout.y > 0.f) ? gout.y : (__expf(gout.y) - 1.f);
        gout.z = (gout.z > 0.f) ? gout.z : (__expf(gout.z) - 1.f);
        gout.w = (gout.w > 0.f) ? gout.w : (__expf(gout.w) - 1.f);
        float4 hv = ((const float4*)(h + node * HID))[l];
        hv.x += gout.x; hv.y += gout.y; hv.z += gout.z; hv.w += gout.w;
        float sum = hv.x + hv.y + hv.z + hv.w;
        float sq  = hv.x*hv.x + hv.y*hv.y + hv.z*hv.z + hv.w*hv.w;
        #pragma unroll
        for (int o = 16; o; o >>= 1) {
            sum += __shfl_xor_sync(0xffffffffu, sum, o);
            sq  += __shfl_xor_sync(0xffffffffu, sq, o);
        }
        const float mu = sum * (1.0f / 128.0f);
        const float var = sq * (1.0f / 128.0f) - mu * mu;
        const float inv = rsqrtf(var + 1e-5f);
        float4 ho;
        ho.x = (hv.x - mu) * inv * g4v.x + b4v.x;
        ho.y = (hv.y - mu) * inv * g4v.y + b4v.y;
        ho.z = (hv.z - mu) * inv * g4v.z + b4v.z;
        ho.w = (hv.w - mu) * inv * g4v.w + b4v.w;
        ((float4*)(h + node * HID))[l] = ho;

        if (attn_out) {
            float* row = attnrow + w * 128;
            ((float4*)row)[l] = make_float4(0.f, 0.f, 0.f, 0.f);
            __syncwarp();
            for (int k = l; k < E1; k += 32) {
                const float4 e4 = ((float4*)mybuf)[k];
                const float val = 0.25f * (e4.x * rs4.x + e4.y * rs4.y +
                                           e4.z * rs4.z + e4.w * rs4.w);
                atomicAdd(&row[src8[sb + k]], val);
            }
            __syncwarp();
            ((float4*)(attn_out + (size_t)b * CNODE * CNODE + (size_t)d * CNODE))[l] =
                ((float4*)row)[l];
            __syncwarp();
        }
    }
}

// ---------------- launch ----------------
extern "C" void kernel_launch(void* const* d_in, const int* in_sizes, int n_in,
                              void* d_out, int out_size) {
    const float* x        = (const float*)d_in[0];
    const void*  ei       = d_in[1];
    const float* emb_W    = (const float*)d_in[2];
    const float* emb_b    = (const float*)d_in[3];
    const float* lin_l_W  = (const float*)d_in[4];
    const float* lin_l_b  = (const float*)d_in[5];
    const float* lin_r_W  = (const float*)d_in[6];
    const float* lin_r_b  = (const float*)d_in[7];
    const float* att      = (const float*)d_in[8];
    const float* gat_bias = (const float*)d_in[9];
    const float* ln_g     = (const float*)d_in[10];
    const float* ln_b     = (const float*)d_in[11];
    const float* proj_W   = (const float*)d_in[12];
    const float* proj_b   = (const float*)d_in[13];
    float* out = (float*)d_out;

    float *Xt, *h, *xl, *xr, *om;
    cudaGetSymbolAddress((void**)&Xt, g_Xt);
    cudaGetSymbolAddress((void**)&h,  g_h);
    cudaGetSymbolAddress((void**)&xl, g_xl);
    cudaGetSymbolAddress((void**)&xr, g_xr);
    cudaGetSymbolAddress((void**)&om, g_om);

    cudaFuncSetAttribute(gat_kernel, cudaFuncAttributeMaxDynamicSharedMemorySize, GAT_SMEM_BYTES);

    build_csr_kernel<<<1, 256>>>(ei);
    transpose_x_kernel<<<dim3(LSEQ / 32, CNODE / 32, BATCH), dim3(32, 8)>>>(x);

    // embed: h = Xt(32768x256) @ emb_W(256x128) + emb_b
    gemm_kernel<<<dim3(1, NNODE / 32), 256>>>(Xt, LSEQ, emb_W, HID, emb_b, h, HID, LSEQ);

    for (int layer = 0; layer < 2; ++layer) {
        gemm_kernel<<<dim3(1, NNODE / 32), 256>>>(h, HID, lin_l_W + layer * HID * HID, HID,
                                                  lin_l_b + layer * HID, xl, HID, HID);
        gemm_kernel<<<dim3(1, NNODE / 32), 256>>>(h, HID, lin_r_W + layer * HID * HID, HID,
                                                  lin_r_b + layer * HID, xr, HID, HID);
        float* attn_ptr = (layer == 1 && out_size >= OUT_ELEMS + ATTN_ELEMS) ? out + OUT_ELEMS : nullptr;
        gat_kernel<<<BATCH, 512, GAT_SMEM_BYTES>>>(h, xl, xr,
                                                   att + layer * HID, gat_bias + layer * HID,
                                                   ln_g + layer * HID, ln_b + layer * HID, attn_ptr);
    }

    // proj: om = h(32768x128) @ proj_W(128x256) + proj_b
    gemm_kernel<<<dim3(LSEQ / 128, NNODE / 32), 256>>>(h, HID, proj_W, LSEQ, proj_b, om, LSEQ, HID);
    transpose_out_kernel<<<dim3(LSEQ / 32, CNODE / 32, BATCH), dim3(32, 8)>>>(out);
}

// round 16
// speedup vs baseline: 1.1641x; 1.1592x over previous
#include <cuda_runtime.h>
#include <cuda_bf16.h>
#include <cstdint>

// ---------------- problem constants ----------------
#define BATCH 256
#define LSEQ  256
#define CNODE 128
#define HID   128
#define NHEAD 4
#define DHEAD 32
#define NEDGE 4096
#define NSLOT (NEDGE + CNODE)               // 4224 incl. self loops
#define NNODE (BATCH * CNODE)               // 32768
#define OUT_ELEMS  (BATCH * LSEQ * CNODE)   // 8388608
#define ATTN_ELEMS (BATCH * CNODE * CNODE)  // 4194304

// ---------------- scratch ----------------
__device__ float g_Xt[NNODE * LSEQ];       // 32 MB  transposed x for embed GEMM
__device__ float g_h[NNODE * HID];         // 16 MB  node features
__device__ float g_xl[NNODE * HID];        // 16 MB
__device__ float g_xr[NNODE * HID];        // 16 MB
__device__ float g_om[NNODE * LSEQ];       // 32 MB  proj output before transpose
__device__ int   g_slot_ptr[CNODE + 1];    // slot CSR (self-loop first per dst)
__device__ int   g_slot_src[NSLOT];

// ---------------- CSR/slot build ----------------
__global__ void build_csr_kernel(const void* __restrict__ eiraw) {
    __shared__ int cnt[CNODE];
    __shared__ int base[CNODE + 1];
    __shared__ int is64_s;
    const long long* e64 = (const long long*)eiraw;
    const int* e32 = (const int*)eiraw;
    int tid = threadIdx.x;

    if (tid == 0) is64_s = 1;
    if (tid < CNODE) cnt[tid] = 0;
    __syncthreads();
    int bad = 0;
    for (int i = tid; i < NEDGE; i += 256) {
        long long v = e64[i];
        if (v < 0 || v >= CNODE) bad = 1;
    }
    if (bad) is64_s = 0;
    __syncthreads();
    const int is64 = is64_s;

    for (int e = tid; e < NEDGE; e += 256) {
        int d = is64 ? (int)e64[NEDGE + e] : e32[NEDGE + e];
        atomicAdd(&cnt[d], 1);
    }
    __syncthreads();
    if (tid == 0) {
        int run = 0;
        for (int i = 0; i < CNODE; ++i) { base[i] = run; run += cnt[i]; }
        base[CNODE] = run;
    }
    __syncthreads();
    if (tid <= CNODE) g_slot_ptr[tid] = base[tid] + tid;
    if (tid < CNODE) {
        g_slot_src[base[tid] + tid] = tid;   // self loop first
        cnt[tid] = base[tid];
    }
    __syncthreads();
    for (int e = tid; e < NEDGE; e += 256) {
        int d = is64 ? (int)e64[NEDGE + e] : e32[NEDGE + e];
        int s = is64 ? (int)e64[e]         : e32[e];
        int pos = atomicAdd(&cnt[d], 1);
        g_slot_src[pos + d + 1] = s;
    }
}

// ---------------- transpose x: (B,L,C) -> Xt[(b*C+c)][l] ----------------
__global__ void transpose_x_kernel(const float* __restrict__ x) {
    __shared__ float tile[32][33];
    int b = blockIdx.z;
    int l0 = blockIdx.x * 32, c0 = blockIdx.y * 32;
    int tx = threadIdx.x, ty = threadIdx.y;
    const float* src = x + (size_t)b * LSEQ * CNODE;
    #pragma unroll
    for (int i = 0; i < 32; i += 8)
        tile[ty + i][tx] = src[(size_t)(l0 + ty + i) * CNODE + c0 + tx];
    __syncthreads();
    float* dst = g_Xt + (size_t)b * CNODE * LSEQ;
    #pragma unroll
    for (int i = 0; i < 32; i += 8)
        dst[(size_t)(c0 + ty + i) * LSEQ + l0 + tx] = tile[tx][ty + i];
}

// ---------------- transpose out: om[(b*C+c)][l] -> out[(b*L+l)][c] ----------------
__global__ void transpose_out_kernel(float* __restrict__ out) {
    __shared__ float tile[32][33];
    int b = blockIdx.z;
    int l0 = blockIdx.x * 32, c0 = blockIdx.y * 32;
    int tx = threadIdx.x, ty = threadIdx.y;
    const float* src = g_om + (size_t)b * CNODE * LSEQ;
    #pragma unroll
    for (int i = 0; i < 32; i += 8)
        tile[ty + i][tx] = src[(size_t)(c0 + ty + i) * LSEQ + l0 + tx];
    __syncthreads();
    float* dst = out + (size_t)b * LSEQ * CNODE;
    #pragma unroll
    for (int i = 0; i < 32; i += 8)
        dst[(size_t)(l0 + ty + i) * CNODE + c0 + tx] = tile[tx][ty + i];
}

// ---------------- bf16-split tensor-core GEMM (mma.sync, sm_80+ PTX) --------
// C(MxN) = A(MxK) @ W(KxN) + bias, fp32 in/out.
// 3-term bf16 split: D = Ah*Bh + Ah*Bl + Al*Bh  (elem err ~2^-16).
// CTA 128x128, 8 warps (warp = 32M x 64N), K chunk 32.
// smem tiles bf16, row stride 40 halves (80 B) -> ldmatrix conflict-free.
#define TPAD 40
#define A_HI_OFF 0
#define A_LO_OFF 10240
#define B_HI_OFF 20480
#define B_LO_OFF 30720

__device__ __forceinline__ void bsplit(float x, uint16_t& hi, uint16_t& lo) {
    __nv_bfloat16 h = __float2bfloat16_rn(x);
    float r = x - __bfloat162float(h);
    __nv_bfloat16 l = __float2bfloat16_rn(r);
    hi = *(uint16_t*)&h;
    lo = *(uint16_t*)&l;
}

#define LDSM4(r0, r1, r2, r3, addr) \
    asm volatile("ldmatrix.sync.aligned.m8n8.x4.shared.b16 {%0,%1,%2,%3}, [%4];" \
                 : "=r"(r0), "=r"(r1), "=r"(r2), "=r"(r3) : "r"(addr))

#define MMA16816(d, a, b0, b1) \
    asm volatile("mma.sync.aligned.m16n8k16.row.col.f32.bf16.bf16.f32 " \
                 "{%0,%1,%2,%3},{%4,%5,%6,%7},{%8,%9},{%0,%1,%2,%3};" \
                 : "+f"((d)[0]), "+f"((d)[1]), "+f"((d)[2]), "+f"((d)[3]) \
                 : "r"((a)[0]), "r"((a)[1]), "r"((a)[2]), "r"((a)[3]), \
                   "r"(b0), "r"(b1))

__global__ __launch_bounds__(256) void gemm_mma(
    const float* __restrict__ A, int lda,
    const float* __restrict__ W, int ldb,
    const float* __restrict__ bias,
    float* __restrict__ C, int ldc, int K)
{
    __shared__ __align__(16) uint8_t smem[40960];
    char* smp = (char*)smem;
    const uint32_t smb = (uint32_t)__cvta_generic_to_shared(smem);

    const int tid = threadIdx.x;
    const int lane = tid & 31, wid = tid >> 5;
    const int m0 = blockIdx.y * 128, n0 = blockIdx.x * 128;
    const int m_off = (wid & 3) * 32;      // warp M offset within CTA
    const int n_off = (wid >> 2) * 64;     // warp N offset within CTA

    float acc[2][8][4];
    #pragma unroll
    for (int i = 0; i < 2; ++i)
        #pragma unroll
        for (int j = 0; j < 8; ++j)
            #pragma unroll
            for (int q = 0; q < 4; ++q) acc[i][j][q] = 0.f;

    // ldmatrix per-lane address offsets (bytes, relative to tile base)
    const uint32_t a_row = lane & 15, a_sel = lane >> 4;           // A: [m][k]
    uint32_t aoff[2];
    #pragma unroll
    for (int mt = 0; mt < 2; ++mt)
        aoff[mt] = ((m_off + mt * 16 + a_row) * TPAD + a_sel * 8) * 2;
    const uint32_t b_row = ((lane >> 4) << 3) + (lane & 7);        // B: [n][k]
    const uint32_t b_sel = (lane >> 3) & 1;
    uint32_t boff[4];
    #pragma unroll
    for (int nt2 = 0; nt2 < 4; ++nt2)
        boff[nt2] = ((n_off + nt2 * 16 + b_row) * TPAD + b_sel * 8) * 2;

    for (int k0 = 0; k0 < K; k0 += 32) {
        // ---- stage A chunk (128m x 32k) as bf16 hi/lo ----
        #pragma unroll
        for (int r = 0; r < 4; ++r) {
            int j = tid + r * 256;
            int m = j >> 3, kq = (j & 7) * 4;
            float4 v = *(const float4*)(A + (size_t)(m0 + m) * lda + k0 + kq);
            uint16_t h0, h1, h2, h3, l0, l1, l2, l3;
            bsplit(v.x, h0, l0); bsplit(v.y, h1, l1);
            bsplit(v.z, h2, l2); bsplit(v.w, h3, l3);
            uint2 hv = make_uint2((uint32_t)h0 | ((uint32_t)h1 << 16),
                                  (uint32_t)h2 | ((uint32_t)h3 << 16));
            uint2 lv = make_uint2((uint32_t)l0 | ((uint32_t)l1 << 16),
                                  (uint32_t)l2 | ((uint32_t)l3 << 16));
            int off = (m * TPAD + kq) * 2;
            *(uint2*)(smp + A_HI_OFF + off) = hv;
            *(uint2*)(smp + A_LO_OFF + off) = lv;
        }
        // ---- stage B chunk: W[k0..k0+32][n0..n0+128] -> Bt[n][k] hi/lo ----
        #pragma unroll
        for (int r = 0; r < 2; ++r) {
            int j = tid + r * 256;
            int k2 = (j >> 5) * 2, n4 = (j & 31) * 4;
            float4 v0 = *(const float4*)(W + (size_t)(k0 + k2) * ldb + n0 + n4);
            float4 v1 = *(const float4*)(W + (size_t)(k0 + k2 + 1) * ldb + n0 + n4);
            const float* f0 = &v0.x;
            const float* f1 = &v1.x;
            #pragma unroll
            for (int q = 0; q < 4; ++q) {
                uint16_t ha, la, hb, lb;
                bsplit(f0[q], ha, la);
                bsplit(f1[q], hb, lb);
                int off = ((n4 + q) * TPAD + k2) * 2;
                *(uint32_t*)(smp + B_HI_OFF + off) = (uint32_t)ha | ((uint32_t)hb << 16);
                *(uint32_t*)(smp + B_LO_OFF + off) = (uint32_t)la | ((uint32_t)lb << 16);
            }
        }
        __syncthreads();
        // ---- 3 split terms: (Ah,Bh), (Ah,Bl), (Al,Bh) ----
        #pragma unroll
        for (int t = 0; t < 3; ++t) {
            const uint32_t Ab = smb + (t == 2 ? A_LO_OFF : A_HI_OFF);
            const uint32_t Bb = smb + (t == 1 ? B_LO_OFF : B_HI_OFF);
            #pragma unroll
            for (int ks = 0; ks < 2; ++ks) {
                uint32_t af[2][4];
                LDSM4(af[0][0], af[0][1], af[0][2], af[0][3], Ab + aoff[0] + ks * 32);
                LDSM4(af[1][0], af[1][1], af[1][2], af[1][3], Ab + aoff[1] + ks * 32);
                #pragma unroll
                for (int nt2 = 0; nt2 < 4; ++nt2) {
                    uint32_t bf[4];
                    LDSM4(bf[0], bf[1], bf[2], bf[3], Bb + boff[nt2] + ks * 32);
                    MMA16816(acc[0][nt2 * 2 + 0], af[0], bf[0], bf[1]);
                    MMA16816(acc[0][nt2 * 2 + 1], af[0], bf[2], bf[3]);
                    MMA16816(acc[1][nt2 * 2 + 0], af[1], bf[0], bf[1]);
                    MMA16816(acc[1][nt2 * 2 + 1], af[1], bf[2], bf[3]);
                }
            }
        }
        __syncthreads();
    }

    // ---- epilogue: D frag rows g,g+8; cols 2i,2i+1 ----
    const int g = lane >> 2, i2 = (lane & 3) * 2;
    #pragma unroll
    for (int mt = 0; mt < 2; ++mt) {
        #pragma unroll
        for (int nt = 0; nt < 8; ++nt) {
            int m = m0 + m_off + mt * 16 + g;
            int n = n0 + n_off + nt * 8 + i2;
            float2 bv = *(const float2*)(bias + n);
            float2 o0 = make_float2(acc[mt][nt][0] + bv.x, acc[mt][nt][1] + bv.y);
            float2 o1 = make_float2(acc[mt][nt][2] + bv.x, acc[mt][nt][3] + bv.y);
            *(float2*)(C + (size_t)m * ldc + n) = o0;
            *(float2*)(C + (size_t)(m + 8) * ldc + n) = o1;
        }
    }
}

// ---------------- GAT layer kernel (warp-per-dst, all warp-local) ----------------
#define XL_F     (CNODE * 132)                 // 16896
#define LBUF_F   (16 * 128 * 4)                // 8192
#define ATTN_F   (16 * 128)                    // 2048
#define A_F      128
#define SMEM_F   (XL_F + LBUF_F + ATTN_F + A_F)
#define SRC_B_OFF (SMEM_F * 4)
#define PTR_B_OFF (SRC_B_OFF + NSLOT)
#define GAT_SMEM_BYTES (PTR_B_OFF + (CNODE + 1) * 4)

__global__ __launch_bounds__(512, 2) void gat_kernel(
    float* __restrict__ h, const float* __restrict__ xl, const float* __restrict__ xr,
    const float* __restrict__ att, const float* __restrict__ gat_bias,
    const float* __restrict__ ln_g, const float* __restrict__ ln_b,
    float* __restrict__ attn_out)
{
    extern __shared__ __align__(16) float sm[];
    float* xl_s   = sm;
    float* lbuf   = sm + XL_F;
    float* attnrow= sm + XL_F + LBUF_F;
    float* a_s    = sm + XL_F + LBUF_F + ATTN_F;
    unsigned char* src8 = (unsigned char*)sm + SRC_B_OFF;
    int* ptr_s = (int*)((char*)sm + PTR_B_OFF);

    const int b = blockIdx.x;
    const int tid = threadIdx.x;
    const int w = tid >> 5;
    const int l = tid & 31;
    const int hh = l >> 3;

    {
        const float4* src4 = (const float4*)(xl + (size_t)b * CNODE * HID);
        for (int i = tid; i < CNODE * 32; i += 512) {
            int node = i >> 5, d4 = i & 31;
            ((float4*)xl_s)[node * 33 + d4] = src4[i];
        }
        for (int i = tid; i < NSLOT; i += 512) src8[i] = (unsigned char)g_slot_src[i];
        if (tid <= CNODE) ptr_s[tid] = g_slot_ptr[tid];
        if (tid < 128) a_s[tid] = att[tid];
    }
    __syncthreads();

    const float4 a4 = ((const float4*)a_s)[l];
    const float4 bias4 = ((const float4*)gat_bias)[l];
    const float4 g4v = ((const float4*)ln_g)[l];
    const float4 b4v = ((const float4*)ln_b)[l];
    float* mybuf = lbuf + w * 512;
    const float4* xls4 = (const float4*)xl_s;

    for (int d = w; d < CNODE; d += 16) {
        const int sb = ptr_s[d];
        int E1 = ptr_s[d + 1] - sb;
        if (E1 > 128) E1 = 128;
        const size_t node = (size_t)b * CNODE + d;
        const float4 xr4 = ((const float4*)(xr + node * HID))[l];

        float m = -1e30f;
        #pragma unroll 2
        for (int k = 0; k < E1; ++k) {
            const int src = src8[sb + k];
            const float4 v = xls4[src * 33 + l];
            float p;
            {
                float t0 = v.x + xr4.x; t0 = fmaxf(t0, 0.2f * t0);
                float t1 = v.y + xr4.y; t1 = fmaxf(t1, 0.2f * t1);
                float t2 = v.z + xr4.z; t2 = fmaxf(t2, 0.2f * t2);
                float t3 = v.w + xr4.w; t3 = fmaxf(t3, 0.2f * t3);
                p = t0 * a4.x + t1 * a4.y + t2 * a4.z + t3 * a4.w;
            }
            p += __shfl_xor_sync(0xffffffffu, p, 4);
            p += __shfl_xor_sync(0xffffffffu, p, 2);
            p += __shfl_xor_sync(0xffffffffu, p, 1);
            if ((l & 7) == 0) mybuf[k * 4 + hh] = p;
            m = fmaxf(m, p);
        }
        __syncwarp();
        float4 m4;
        m4.x = __shfl_sync(0xffffffffu, m, 0);
        m4.y = __shfl_sync(0xffffffffu, m, 8);
        m4.z = __shfl_sync(0xffffffffu, m, 16);
        m4.w = __shfl_sync(0xffffffffu, m, 24);

        float4 s4 = {0.f, 0.f, 0.f, 0.f};
        for (int k = l; k < E1; k += 32) {
            float4 f = ((float4*)mybuf)[k];
            f.x = __expf(f.x - m4.x);
            f.y = __expf(f.y - m4.y);
            f.z = __expf(f.z - m4.z);
            f.w = __expf(f.w - m4.w);
            ((float4*)mybuf)[k] = f;
            s4.x += f.x; s4.y += f.y; s4.z += f.z; s4.w += f.w;
        }
        #pragma unroll
        for (int o = 16; o; o >>= 1) {
            s4.x += __shfl_xor_sync(0xffffffffu, s4.x, o);
            s4.y += __shfl_xor_sync(0xffffffffu, s4.y, o);
            s4.z += __shfl_xor_sync(0xffffffffu, s4.z, o);
            s4.w += __shfl_xor_sync(0xffffffffu, s4.w, o);
        }
        float4 rs4;
        rs4.x = 1.0f / (s4.x + 1e-16f);
        rs4.y = 1.0f / (s4.y + 1e-16f);
        rs4.z = 1.0f / (s4.z + 1e-16f);
        rs4.w = 1.0f / (s4.w + 1e-16f);
        const float rs_m = (hh == 0) ? rs4.x : (hh == 1) ? rs4.y : (hh == 2) ? rs4.z : rs4.w;
        __syncwarp();

        float4 acc = {0.f, 0.f, 0.f, 0.f};
        #pragma unroll 2
        for (int k = 0; k < E1; ++k) {
            const int src = src8[sb + k];
            const float e = mybuf[k * 4 + hh];
            const float4 v = xls4[src * 33 + l];
            acc.x += e * v.x; acc.y += e * v.y; acc.z += e * v.z; acc.w += e * v.w;
        }
        float4 gout;
        gout.x = acc.x * rs_m + bias4.x;
        gout.y = acc.y * rs_m + bias4.y;
        gout.z = acc.z * rs_m + bias4.z;
        gout.w = acc.w * rs_m + bias4.w;
        gout.x = (gout.x > 0.f) ? gout.x : (__expf(gout.x) - 1.f);
        gout.y = (gout.y > 0.f) ? gout.y : (__expf(gout.y) - 1.f);
        gout.z = (gout.z > 0.f) ? gout.z : (__expf(gout.z) - 1.f);
        gout.w = (gout.w > 0.f) ? gout.w : (__expf(gout.w) - 1.f);
        float4 hv = ((const float4*)(h + node * HID))[l];
        hv.x += gout.x; hv.y += gout.y; hv.z += gout.z; hv.w += gout.w;
        float sum = hv.x + hv.y + hv.z + hv.w;
        float sq  = hv.x*hv.x + hv.y*hv.y + hv.z*hv.z + hv.w*hv.w;
        #pragma unroll
        for (int o = 16; o; o >>= 1) {
            sum += __shfl_xor_sync(0xffffffffu, sum, o);
            sq  += __shfl_xor_sync(0xffffffffu, sq, o);
        }
        const float mu = sum * (1.0f / 128.0f);
        const float var = sq * (1.0f / 128.0f) - mu * mu;
        const float inv = rsqrtf(var + 1e-5f);
        float4 ho;
        ho.x = (hv.x - mu) * inv * g4v.x + b4v.x;
        ho.y = (hv.y - mu) * inv * g4v.y + b4v.y;
        ho.z = (hv.z - mu) * inv * g4v.z + b4v.z;
        ho.w = (hv.w - mu) * inv * g4v.w + b4v.w;
        ((float4*)(h + node * HID))[l] = ho;

        if (attn_out) {
            float* row = attnrow + w * 128;
            ((float4*)row)[l] = make_float4(0.f, 0.f, 0.f, 0.f);
            __syncwarp();
            for (int k = l; k < E1; k += 32) {
                const float4 e4 = ((float4*)mybuf)[k];
                const float val = 0.25f * (e4.x * rs4.x + e4.y * rs4.y +
                                           e4.z * rs4.z + e4.w * rs4.w);
                atomicAdd(&row[src8[sb + k]], val);
            }
            __syncwarp();
            ((float4*)(attn_out + (size_t)b * CNODE * CNODE + (size_t)d * CNODE))[l] =
                ((float4*)row)[l];
            __syncwarp();
        }
    }
}

// ---------------- launch ----------------
extern "C" void kernel_launch(void* const* d_in, const int* in_sizes, int n_in,
                              void* d_out, int out_size) {
    const float* x        = (const float*)d_in[0];
    const void*  ei       = d_in[1];
    const float* emb_W    = (const float*)d_in[2];
    const float* emb_b    = (const float*)d_in[3];
    const float* lin_l_W  = (const float*)d_in[4];
    const float* lin_l_b  = (const float*)d_in[5];
    const float* lin_r_W  = (const float*)d_in[6];
    const float* lin_r_b  = (const float*)d_in[7];
    const float* att      = (const float*)d_in[8];
    const float* gat_bias = (const float*)d_in[9];
    const float* ln_g     = (const float*)d_in[10];
    const float* ln_b     = (const float*)d_in[11];
    const float* proj_W   = (const float*)d_in[12];
    const float* proj_b   = (const float*)d_in[13];
    float* out = (float*)d_out;

    float *Xt, *h, *xl, *xr, *om;
    cudaGetSymbolAddress((void**)&Xt, g_Xt);
    cudaGetSymbolAddress((void**)&h,  g_h);
    cudaGetSymbolAddress((void**)&xl, g_xl);
    cudaGetSymbolAddress((void**)&xr, g_xr);
    cudaGetSymbolAddress((void**)&om, g_om);

    cudaFuncSetAttribute(gat_kernel, cudaFuncAttributeMaxDynamicSharedMemorySize, GAT_SMEM_BYTES);

    build_csr_kernel<<<1, 256>>>(ei);
    transpose_x_kernel<<<dim3(LSEQ / 32, CNODE / 32, BATCH), dim3(32, 8)>>>(x);

    // embed: h = Xt(32768x256) @ emb_W(256x128) + emb_b
    gemm_mma<<<dim3(1, NNODE / 128), 256>>>(Xt, LSEQ, emb_W, HID, emb_b, h, HID, LSEQ);

    for (int layer = 0; layer < 2; ++layer) {
        gemm_mma<<<dim3(1, NNODE / 128), 256>>>(h, HID, lin_l_W + layer * HID * HID, HID,
                                                lin_l_b + layer * HID, xl, HID, HID);
        gemm_mma<<<dim3(1, NNODE / 128), 256>>>(h, HID, lin_r_W + layer * HID * HID, HID,
                                                lin_r_b + layer * HID, xr, HID, HID);
        float* attn_ptr = (layer == 1 && out_size >= OUT_ELEMS + ATTN_ELEMS) ? out + OUT_ELEMS : nullptr;
        gat_kernel<<<BATCH, 512, GAT_SMEM_BYTES>>>(h, xl, xr,
                                                   att + layer * HID, gat_bias + layer * HID,
                                                   ln_g + layer * HID, ln_b + layer * HID, attn_ptr);
    }

    // proj: om = h(32768x128) @ proj_W(128x256) + proj_b
    gemm_mma<<<dim3(LSEQ / 128, NNODE / 128), 256>>>(h, HID, proj_W, LSEQ, proj_b, om, LSEQ, HID);
    transpose_out_kernel<<<dim3(LSEQ / 32, CNODE / 32, BATCH), dim3(32, 8)>>>(out);
}